// round 15
// baseline (speedup 1.0000x reference)
#include <cuda_runtime.h>
#include <cuda_bf16.h>
#include <cstdint>

// ---------------- problem constants ----------------
#define BB    16
#define NPTS  4096
#define MPTS  1024
#define C1CH  128
#define C2CH  256
#define KIN   384          // C1 + C2
#define OC    256          // MLP0 == MLP1 == 256
#define ROWS  (BB * NPTS)  // 65536
#define EPSBN 1e-5f
#define NBLK  512          // GEMM row-blocks (ROWS/128) -> BN partial count

// ---------------- device scratch (static, allocation-free, 16B aligned) ----------------
__device__ __align__(16) float g_p2t[BB * MPTS * C2CH];
__device__ __align__(16) __nv_bfloat16 g_featH[ROWS * KIN];
__device__ __align__(16) __nv_bfloat16 g_featL[ROWS * KIN];
__device__ __align__(16) int   g_idx[ROWS * 3];
__device__ __align__(16) float g_wgt[ROWS * 3];
__device__ __align__(16) float g_h1[ROWS * OC];
__device__ __align__(16) __nv_bfloat16 g_h1H[ROWS * OC];
__device__ __align__(16) __nv_bfloat16 g_h1L[ROWS * OC];
__device__ __align__(16) float g_h2[ROWS * OC];
__device__ __align__(16) __nv_bfloat16 g_w1h[OC * KIN], g_w1l[OC * KIN];
__device__ __align__(16) __nv_bfloat16 g_w2h[OC * OC],  g_w2l[OC * OC];
__device__ __align__(16) float g_ps1[NBLK * OC], g_pq1[NBLK * OC];
__device__ __align__(16) float g_ps2[NBLK * OC], g_pq2[NBLK * OC];
__device__ __align__(16) float g_scale1[OC], g_bias1[OC];
__device__ __align__(16) float g_scale2[OC], g_bias2[OC];

// ---------------- helpers ----------------
__device__ __forceinline__ uint32_t smem_u32(const void* p) {
    uint32_t a;
    asm("{ .reg .u64 t; cvta.to.shared.u64 t, %1; cvt.u32.u64 %0, t; }" : "=r"(a) : "l"(p));
    return a;
}
#define CP16(dst, src) \
    asm volatile("cp.async.cg.shared.global [%0], [%1], 16;" :: "r"(dst), "l"(src) : "memory")
#define CP_COMMIT()  asm volatile("cp.async.commit_group;" ::: "memory")
#define CP_WAIT0()   asm volatile("cp.async.wait_group 0;" ::: "memory")

__device__ __forceinline__ void ldm_x4(uint32_t* r, uint32_t addr) {
    asm volatile("ldmatrix.sync.aligned.m8n8.x4.shared.b16 {%0,%1,%2,%3}, [%4];"
        : "=r"(r[0]), "=r"(r[1]), "=r"(r[2]), "=r"(r[3]) : "r"(addr));
}

__device__ __forceinline__ void mma16816(float* d, const uint32_t* a, const uint32_t* b) {
    asm volatile("mma.sync.aligned.m16n8k16.row.col.f32.bf16.bf16.f32 "
        "{%0,%1,%2,%3}, {%4,%5,%6,%7}, {%8,%9}, {%0,%1,%2,%3};"
        : "+f"(d[0]), "+f"(d[1]), "+f"(d[2]), "+f"(d[3])
        : "r"(a[0]), "r"(a[1]), "r"(a[2]), "r"(a[3]), "r"(b[0]), "r"(b[1]));
}

__device__ __forceinline__ void split_bf16(float v, __nv_bfloat16& h, __nv_bfloat16& l) {
    h = __float2bfloat16(v);
    l = __float2bfloat16(v - __bfloat162float(h));
}

// ---------------- transpose points2: (B, C2, M) -> (B, M, C2) ----------------
__global__ void k_transpose_p2(const float* __restrict__ p2) {
    __shared__ float tile[32][33];
    const int b  = blockIdx.z;
    const int m0 = blockIdx.x * 32, c0 = blockIdx.y * 32;
    const int tx = threadIdx.x, ty = threadIdx.y;
    const float* in = p2 + (size_t)b * C2CH * MPTS;
#pragma unroll
    for (int i = 0; i < 4; i++)
        tile[ty + i * 8][tx] = in[(size_t)(c0 + ty + i * 8) * MPTS + m0 + tx];
    __syncthreads();
    float* out = g_p2t + (size_t)b * MPTS * C2CH;
#pragma unroll
    for (int i = 0; i < 4; i++)
        out[(size_t)(m0 + ty + i * 8) * C2CH + c0 + tx] = tile[tx][ty + i * 8];
}

// ---------------- transpose points1 -> split-bf16 feat cols [256..384) ----------------
__global__ void k_transpose_p1(const float* __restrict__ p1) {
    __shared__ float tile[32][33];
    const int b  = blockIdx.z;
    const int n0 = blockIdx.x * 32, c0 = blockIdx.y * 32;
    const int tx = threadIdx.x, ty = threadIdx.y;
    const float* in = p1 + (size_t)b * C1CH * NPTS;
#pragma unroll
    for (int i = 0; i < 4; i++)
        tile[ty + i * 8][tx] = in[(size_t)(c0 + ty + i * 8) * NPTS + n0 + tx];
    __syncthreads();
#pragma unroll
    for (int i = 0; i < 4; i++) {
        const int n = n0 + ty + i * 8;
        const size_t o = (size_t)(b * NPTS + n) * KIN + C2CH + c0 + tx;
        __nv_bfloat16 h, l;
        split_bf16(tile[tx][ty + i * 8], h, l);
        g_featH[o] = h; g_featL[o] = l;
    }
}

// ---------------- 3-NN over M=1024 (xyz2 staged in SMEM) ----------------
__global__ void k_knn(const float* __restrict__ xyz1, const float* __restrict__ xyz2) {
    __shared__ float4 s2[MPTS];
    const int b   = blockIdx.y;
    const int tid = threadIdx.x;
    const float* x2 = xyz2 + (size_t)b * 3 * MPTS;
    for (int m = tid; m < MPTS; m += 256)
        s2[m] = make_float4(x2[m], x2[m + MPTS], x2[m + 2 * MPTS], 0.f);
    __syncthreads();

    const int n = blockIdx.x * 256 + tid;
    const float* x1 = xyz1 + (size_t)b * 3 * NPTS;
    const float px = x1[n], py = x1[n + NPTS], pz = x1[n + 2 * NPTS];

    float d0 = 3.4e38f, d1 = 3.4e38f, d2 = 3.4e38f;
    int   i0 = 0, i1 = 0, i2 = 0;
#pragma unroll 4
    for (int m = 0; m < MPTS; m++) {
        const float4 q = s2[m];
        const float dx = px - q.x, dy = py - q.y, dz = pz - q.z;
        const float d = fmaf(dx, dx, fmaf(dy, dy, dz * dz));
        if (d < d2) {
            if (d < d1) {
                d2 = d1; i2 = i1;
                if (d < d0) { d1 = d0; i1 = i0; d0 = d; i0 = m; }
                else        { d1 = d;  i1 = m; }
            } else { d2 = d; i2 = m; }
        }
    }
    d0 = fmaxf(d0, 1e-10f); d1 = fmaxf(d1, 1e-10f); d2 = fmaxf(d2, 1e-10f);
    const float w0 = 1.f / d0, w1 = 1.f / d1, w2 = 1.f / d2;
    const float inv = 1.f / (w0 + w1 + w2);
    const int row = b * NPTS + n;
    g_idx[row * 3 + 0] = i0; g_idx[row * 3 + 1] = i1; g_idx[row * 3 + 2] = i2;
    g_wgt[row * 3 + 0] = w0 * inv; g_wgt[row * 3 + 1] = w1 * inv; g_wgt[row * 3 + 2] = w2 * inv;
}

// -------- weighted gather -> split-bf16 feat cols [0..256) (warp per row) --------
__global__ void k_interp() {
    const int tid  = threadIdx.x;
    const int warp = tid >> 5, lane = tid & 31;
    const int row  = blockIdx.x * 4 + warp;
    const int b    = row >> 12;
    const int i0 = g_idx[row * 3 + 0], i1 = g_idx[row * 3 + 1], i2 = g_idx[row * 3 + 2];
    const float w0 = g_wgt[row * 3 + 0], w1 = g_wgt[row * 3 + 1], w2 = g_wgt[row * 3 + 2];
    const float4* f0 = (const float4*)(g_p2t + ((size_t)b * MPTS + i0) * C2CH);
    const float4* f1 = (const float4*)(g_p2t + ((size_t)b * MPTS + i1) * C2CH);
    const float4* f2 = (const float4*)(g_p2t + ((size_t)b * MPTS + i2) * C2CH);
    union { __nv_bfloat16 b8[8]; uint4 u; } uh, ul;
#pragma unroll
    for (int half = 0; half < 2; half++) {
        const int j = lane * 2 + half;
        const float4 a = f0[j], c = f1[j], e = f2[j];
        float r[4];
        r[0] = fmaf(w0, a.x, fmaf(w1, c.x, w2 * e.x));
        r[1] = fmaf(w0, a.y, fmaf(w1, c.y, w2 * e.y));
        r[2] = fmaf(w0, a.z, fmaf(w1, c.z, w2 * e.z));
        r[3] = fmaf(w0, a.w, fmaf(w1, c.w, w2 * e.w));
#pragma unroll
        for (int q = 0; q < 4; q++)
            split_bf16(r[q], uh.b8[half * 4 + q], ul.b8[half * 4 + q]);
    }
    const size_t o = (size_t)row * KIN + lane * 8;
    *(uint4*)(g_featH + o) = uh.u;
    *(uint4*)(g_featL + o) = ul.u;
}

// ---------------- weight split prep ----------------
__global__ void k_prep_w(const float* __restrict__ W1, const float* __restrict__ W2) {
    const int i = blockIdx.x * 256 + threadIdx.x;
    if (i < OC * KIN) split_bf16(W1[i], g_w1h[i], g_w1l[i]);
    if (i < OC * OC)  split_bf16(W2[i], g_w2h[i], g_w2l[i]);
}

// ---------------- bf16x3-split GEMM via mma.sync: C = A(ROWSxK) * W(OCxK)^T ----
// CTA 128x128, 8 warps (4m x 2n), warp tile 32x64. K=32 stages (two K16 halves
// per barrier -> HALF the syncs of R14), double-buffered cp.async into DYNAMIC
// smem (2 x 40KB). Rows padded to 80B: 80k mod 128 spans 8 distinct 16B banks,
// so ldmatrix stays conflict-free. Epilogue emits deterministic per-CTA BN
// partials (fused stats, R14-proven). Pointers bound in device code.
#define ARR  (128 * 80)            // bytes per matrix array per buffer (10240)
#define BUFB (4 * ARR)             // 40960
#define SMEM_DYN (2 * BUFB)        // 81920

template <int KDIM>
__device__ __forceinline__ void gemm_body(
        const __nv_bfloat16* __restrict__ Ah_, const __nv_bfloat16* __restrict__ Al_,
        const __nv_bfloat16* __restrict__ Wh_, const __nv_bfloat16* __restrict__ Wl_,
        float* __restrict__ C, float* __restrict__ psum, float* __restrict__ psq) {
    extern __shared__ __align__(16) char dsm[];        // [2][Ah|Al|Bh|Bl] 80B rows
    const int tid  = threadIdx.x;
    const int lane = tid & 31, wid = tid >> 5;
    const int warp_m = wid & 3, warp_n = wid >> 2;
    const int row0 = blockIdx.y * 128, col0 = blockIdx.x * 128;

    // loader mapping: 4 groups of 64 threads, 2 rows each, 32 bf16 (64B) per row
    const int arr = tid >> 6;              // 0:Ah 1:Al 2:Bh 3:Bl
    const int r2  = (tid & 63) * 2;
    const __nv_bfloat16* g0 = (arr == 0) ? Ah_ : (arr == 1) ? Al_ : (arr == 2) ? Wh_ : Wl_;
    const __nv_bfloat16* gp = g0 + (size_t)((arr < 2 ? row0 : col0) + r2) * KDIM;
    const uint32_t sbase = smem_u32(dsm);
    const uint32_t sdst0 = sbase + (uint32_t)(arr * ARR + r2 * 80);

    // ldmatrix lane addressing (byte offsets within one matrix array; +kh*32 per K16 half)
    const uint32_t aoff = (uint32_t)((warp_m * 32 + (lane & 15)) * 80 + ((lane & 16) ? 16 : 0));
    const uint32_t boff = (uint32_t)((warp_n * 64 + (lane & 7) + ((lane & 16) ? 8 : 0)) * 80
                                     + ((lane & 8) ? 16 : 0));
    // mma fragment lane decomposition (for epilogue addressing)
    const int qm = lane >> 2, qk = (lane & 3) * 2;

    float acc[2][8][4];
#pragma unroll
    for (int i = 0; i < 2; i++)
#pragma unroll
        for (int j = 0; j < 8; j++)
#pragma unroll
            for (int q = 0; q < 4; q++) acc[i][j][q] = 0.f;

    // prologue: stage 0 -> buf 0 (2 rows x 64B each)
#pragma unroll
    for (int i = 0; i < 4; i++) {
        CP16(sdst0 + i * 16,      gp + i * 8);
        CP16(sdst0 + 80 + i * 16, gp + KDIM + i * 8);
    }
    CP_COMMIT();

    constexpr int NS = KDIM / 32;
    for (int t = 0; t < NS; t++) {
        const int buf = t & 1;
        CP_WAIT0();
        __syncthreads();
        if (t + 1 < NS) {
            const uint32_t d = sdst0 + (buf ^ 1) * BUFB;
            const __nv_bfloat16* gs = gp + (t + 1) * 32;
#pragma unroll
            for (int i = 0; i < 4; i++) {
                CP16(d + i * 16,      gs + i * 8);
                CP16(d + 80 + i * 16, gs + KDIM + i * 8);
            }
            CP_COMMIT();
        }

        const uint32_t sb = sbase + buf * BUFB;
#pragma unroll
        for (int kh = 0; kh < 2; kh++) {               // two K16 halves per barrier
            const uint32_t ko = kh * 32;               // byte offset of K16 half
            uint32_t aH[2][4], aL[2][4], bH[8][2], bL[8][2];
#pragma unroll
            for (int mt = 0; mt < 2; mt++) {
                ldm_x4(aH[mt], sb + 0 * ARR + aoff + ko + mt * (16 * 80));
                ldm_x4(aL[mt], sb + 1 * ARR + aoff + ko + mt * (16 * 80));
            }
#pragma unroll
            for (int np = 0; np < 4; np++) {
                uint32_t q[4];
                ldm_x4(q, sb + 2 * ARR + boff + ko + np * (16 * 80));
                bH[2 * np][0] = q[0]; bH[2 * np][1] = q[1];
                bH[2 * np + 1][0] = q[2]; bH[2 * np + 1][1] = q[3];
                ldm_x4(q, sb + 3 * ARR + boff + ko + np * (16 * 80));
                bL[2 * np][0] = q[0]; bL[2 * np][1] = q[1];
                bL[2 * np + 1][0] = q[2]; bL[2 * np + 1][1] = q[3];
            }
#pragma unroll
            for (int mt = 0; mt < 2; mt++)
#pragma unroll
                for (int nt = 0; nt < 8; nt++) {
                    mma16816(acc[mt][nt], aH[mt], bH[nt]);
                    mma16816(acc[mt][nt], aL[mt], bH[nt]);
                    mma16816(acc[mt][nt], aH[mt], bL[nt]);
                }
        }
    }

    // ---- epilogue: store C ----
#pragma unroll
    for (int mt = 0; mt < 2; mt++) {
#pragma unroll
        for (int nt = 0; nt < 8; nt++) {
            const int r = row0 + warp_m * 32 + mt * 16 + qm;
            const int c = col0 + warp_n * 64 + nt * 8 + qk;
            *(float2*)&C[(size_t)r * OC + c]       = make_float2(acc[mt][nt][0], acc[mt][nt][1]);
            *(float2*)&C[(size_t)(r + 8) * OC + c] = make_float2(acc[mt][nt][2], acc[mt][nt][3]);
        }
    }

    // ---- fused deterministic BN partial stats (per-CTA col sums over 128 rows) ----
    __syncthreads();                       // all warps done reading dsm -> reuse as scratch
    float* scr = (float*)dsm;              // [0..511]: sums, [512..1023]: sumsq (8 warps x 64)
#pragma unroll
    for (int nt = 0; nt < 8; nt++) {
        float s0 = acc[0][nt][0] + acc[0][nt][2] + acc[1][nt][0] + acc[1][nt][2];
        float s1 = acc[0][nt][1] + acc[0][nt][3] + acc[1][nt][1] + acc[1][nt][3];
        float q0 = acc[0][nt][0] * acc[0][nt][0] + acc[0][nt][2] * acc[0][nt][2]
                 + acc[1][nt][0] * acc[1][nt][0] + acc[1][nt][2] * acc[1][nt][2];
        float q1 = acc[0][nt][1] * acc[0][nt][1] + acc[0][nt][3] * acc[0][nt][3]
                 + acc[1][nt][1] * acc[1][nt][1] + acc[1][nt][3] * acc[1][nt][3];
#pragma unroll
        for (int d = 16; d >= 4; d >>= 1) {           // reduce over the 8 qm lanes
            s0 += __shfl_down_sync(0xffffffffu, s0, d);
            s1 += __shfl_down_sync(0xffffffffu, s1, d);
            q0 += __shfl_down_sync(0xffffffffu, q0, d);
            q1 += __shfl_down_sync(0xffffffffu, q1, d);
        }
        if (lane < 4) {
            const int l64 = nt * 8 + lane * 2;
            scr[wid * 64 + l64]           = s0;
            scr[wid * 64 + l64 + 1]       = s1;
            scr[512 + wid * 64 + l64]     = q0;
            scr[512 + wid * 64 + l64 + 1] = q1;
        }
    }
    __syncthreads();
    if (tid < 128) {                       // one thread per CTA-local column
        const int half = tid >> 6, l64 = tid & 63;
        float s = 0.f, q = 0.f;
#pragma unroll
        for (int wm = 0; wm < 4; wm++) {   // fixed order -> deterministic
            s += scr[(half * 4 + wm) * 64 + l64];
            q += scr[512 + (half * 4 + wm) * 64 + l64];
        }
        psum[blockIdx.y * OC + col0 + tid] = s;
        psq [blockIdx.y * OC + col0 + tid] = q;
    }
}

// device-side binding of the global scratch buffers
__global__ __launch_bounds__(256, 2) void k_gemm1_mma() {
    gemm_body<KIN>(g_featH, g_featL, g_w1h, g_w1l, g_h1, g_ps1, g_pq1);
}
__global__ __launch_bounds__(256, 2) void k_gemm2_mma() {
    gemm_body<OC>(g_h1H, g_h1L, g_w2h, g_w2l, g_h2, g_ps2, g_pq2);
}

// ---------------- BN finalize: reduce 512 partial blocks, fixed order ----------------
__device__ __forceinline__ void fin_body(const float* __restrict__ psum,
                                         const float* __restrict__ psq,
                                         const float* __restrict__ gamma,
                                         const float* __restrict__ beta,
                                         float* __restrict__ scale,
                                         float* __restrict__ bias) {
    const int c = threadIdx.x;
    float s = 0.f, q = 0.f;
    for (int i = 0; i < NBLK; i++) { s += psum[i * OC + c]; q += psq[i * OC + c]; }
    const float invN = 1.f / (float)ROWS;
    const float mean = s * invN;
    const float var  = q * invN - mean * mean;
    const float sc   = gamma[c] * rsqrtf(var + EPSBN);
    scale[c] = sc;
    bias[c]  = fmaf(-mean, sc, beta[c]);
}
__global__ void k_fin1(const float* __restrict__ g, const float* __restrict__ b) {
    fin_body(g_ps1, g_pq1, g, b, g_scale1, g_bias1);
}
__global__ void k_fin2(const float* __restrict__ g, const float* __restrict__ b) {
    fin_body(g_ps2, g_pq2, g, b, g_scale2, g_bias2);
}

// ---------------- BN1+ReLU -> split-bf16 GEMM2 input ----------------
__global__ void k_bnrelu1() {
    const size_t idx = ((size_t)blockIdx.x * 256 + threadIdx.x) * 4;
    const int c0 = (int)(idx & (OC - 1));
    const float4 v  = *(const float4*)(g_h1 + idx);
    const float4 sc = *(const float4*)(g_scale1 + c0);
    const float4 bi = *(const float4*)(g_bias1 + c0);
    float r[4];
    r[0] = fmaxf(fmaf(v.x, sc.x, bi.x), 0.f);
    r[1] = fmaxf(fmaf(v.y, sc.y, bi.y), 0.f);
    r[2] = fmaxf(fmaf(v.z, sc.z, bi.z), 0.f);
    r[3] = fmaxf(fmaf(v.w, sc.w, bi.w), 0.f);
    union { __nv_bfloat16 b4[4]; uint2 u; } uh, ul;
#pragma unroll
    for (int q = 0; q < 4; q++) split_bf16(r[q], uh.b4[q], ul.b4[q]);
    *(uint2*)(g_h1H + idx) = uh.u;
    *(uint2*)(g_h1L + idx) = ul.u;
}

// ---------------- BN2+ReLU + transpose to (B, 256, N) ----------------
__global__ void k_out(float* __restrict__ out) {
    __shared__ float tile[32][33];
    const int b  = blockIdx.z;
    const int n0 = blockIdx.x * 32, c0 = blockIdx.y * 32;
    const int tx = threadIdx.x, ty = threadIdx.y;
#pragma unroll
    for (int i = 0; i < 4; i++) {
        const int n = n0 + ty + i * 8, c = c0 + tx;
        const float v = g_h2[(size_t)(b * NPTS + n) * OC + c];
        tile[ty + i * 8][tx] = fmaxf(fmaf(v, g_scale2[c], g_bias2[c]), 0.f);
    }
    __syncthreads();
    float* o = out + (size_t)b * OC * NPTS;
#pragma unroll
    for (int i = 0; i < 4; i++)
        o[(size_t)(c0 + ty + i * 8) * NPTS + n0 + tx] = tile[tx][ty + i * 8];
}

// ---------------- launch (only harness pointers cross the host/device boundary) ----
extern "C" void kernel_launch(void* const* d_in, const int* in_sizes, int n_in,
                              void* d_out, int out_size) {
    const float* xyz1    = (const float*)d_in[0];
    const float* xyz2    = (const float*)d_in[1];
    const float* points1 = (const float*)d_in[2];
    const float* points2 = (const float*)d_in[3];
    const float* W1      = (const float*)d_in[4];
    const float* gamma1  = (const float*)d_in[5];
    const float* beta1   = (const float*)d_in[6];
    const float* W2      = (const float*)d_in[7];
    const float* gamma2  = (const float*)d_in[8];
    const float* beta2   = (const float*)d_in[9];
    float* out = (float*)d_out;

    cudaFuncSetAttribute(k_gemm1_mma, cudaFuncAttributeMaxDynamicSharedMemorySize, SMEM_DYN);
    cudaFuncSetAttribute(k_gemm2_mma, cudaFuncAttributeMaxDynamicSharedMemorySize, SMEM_DYN);

    k_transpose_p2<<<dim3(MPTS / 32, C2CH / 32, BB), dim3(32, 8)>>>(points2);
    k_knn<<<dim3(NPTS / 256, BB), 256>>>(xyz1, xyz2);
    k_interp<<<ROWS / 4, 128>>>();
    k_transpose_p1<<<dim3(NPTS / 32, C1CH / 32, BB), dim3(32, 8)>>>(points1);
    k_prep_w<<<(OC * KIN + 255) / 256, 256>>>(W1, W2);

    k_gemm1_mma<<<dim3(OC / 128, ROWS / 128), 256, SMEM_DYN>>>();
    k_fin1<<<1, 256>>>(gamma1, beta1);
    k_bnrelu1<<<(ROWS * OC) / 1024, 256>>>();

    k_gemm2_mma<<<dim3(OC / 128, ROWS / 128), 256, SMEM_DYN>>>();
    k_fin2<<<1, 256>>>(gamma2, beta2);

    k_out<<<dim3(NPTS / 32, OC / 32, BB), dim3(32, 8)>>>(out);
}

// round 16
// speedup vs baseline: 1.4927x; 1.4927x over previous
#include <cuda_runtime.h>
#include <cuda_bf16.h>
#include <cstdint>

// ---------------- problem constants ----------------
#define BB    16
#define NPTS  4096
#define MPTS  1024
#define C1CH  128
#define C2CH  256
#define KIN   384          // C1 + C2
#define OC    256          // MLP0 == MLP1 == 256
#define ROWS  (BB * NPTS)  // 65536
#define EPSBN 1e-5f
#define NBLK  512          // GEMM row-blocks (ROWS/128) -> BN partial count

// ---------------- device scratch (static, allocation-free, 16B aligned) ----------------
__device__ __align__(16) float g_p2t[BB * MPTS * C2CH];
__device__ __align__(16) __nv_bfloat16 g_featH[ROWS * KIN];
__device__ __align__(16) __nv_bfloat16 g_featL[ROWS * KIN];
__device__ __align__(16) int   g_idx[ROWS * 3];
__device__ __align__(16) float g_wgt[ROWS * 3];
__device__ __align__(16) float g_h1[ROWS * OC];
__device__ __align__(16) float g_h2[ROWS * OC];
__device__ __align__(16) __nv_bfloat16 g_w1h[OC * KIN], g_w1l[OC * KIN];
__device__ __align__(16) __nv_bfloat16 g_w2h[OC * OC],  g_w2l[OC * OC];
__device__ __align__(16) float g_ps1[NBLK * OC], g_pq1[NBLK * OC];
__device__ __align__(16) float g_ps2[NBLK * OC], g_pq2[NBLK * OC];
__device__ __align__(16) float g_scale1[OC], g_bias1[OC];
__device__ __align__(16) float g_scale2[OC], g_bias2[OC];

// ---------------- helpers ----------------
__device__ __forceinline__ uint32_t smem_u32(const void* p) {
    uint32_t a;
    asm("{ .reg .u64 t; cvta.to.shared.u64 t, %1; cvt.u32.u64 %0, t; }" : "=r"(a) : "l"(p));
    return a;
}
#define CP16(dst, src) \
    asm volatile("cp.async.cg.shared.global [%0], [%1], 16;" :: "r"(dst), "l"(src) : "memory")
#define CP_COMMIT()  asm volatile("cp.async.commit_group;" ::: "memory")
#define CP_WAIT0()   asm volatile("cp.async.wait_group 0;" ::: "memory")

__device__ __forceinline__ void ldm_x4(uint32_t* r, uint32_t addr) {
    asm volatile("ldmatrix.sync.aligned.m8n8.x4.shared.b16 {%0,%1,%2,%3}, [%4];"
        : "=r"(r[0]), "=r"(r[1]), "=r"(r[2]), "=r"(r[3]) : "r"(addr));
}

__device__ __forceinline__ void mma16816(float* d, const uint32_t* a, const uint32_t* b) {
    asm volatile("mma.sync.aligned.m16n8k16.row.col.f32.bf16.bf16.f32 "
        "{%0,%1,%2,%3}, {%4,%5,%6,%7}, {%8,%9}, {%0,%1,%2,%3};"
        : "+f"(d[0]), "+f"(d[1]), "+f"(d[2]), "+f"(d[3])
        : "r"(a[0]), "r"(a[1]), "r"(a[2]), "r"(a[3]), "r"(b[0]), "r"(b[1]));
}

__device__ __forceinline__ void split_bf16(float v, __nv_bfloat16& h, __nv_bfloat16& l) {
    h = __float2bfloat16(v);
    l = __float2bfloat16(v - __bfloat162float(h));
}

// ---------------- transpose points2: (B, C2, M) -> (B, M, C2) ----------------
__global__ void k_transpose_p2(const float* __restrict__ p2) {
    __shared__ float tile[32][33];
    const int b  = blockIdx.z;
    const int m0 = blockIdx.x * 32, c0 = blockIdx.y * 32;
    const int tx = threadIdx.x, ty = threadIdx.y;
    const float* in = p2 + (size_t)b * C2CH * MPTS;
#pragma unroll
    for (int i = 0; i < 4; i++)
        tile[ty + i * 8][tx] = in[(size_t)(c0 + ty + i * 8) * MPTS + m0 + tx];
    __syncthreads();
    float* out = g_p2t + (size_t)b * MPTS * C2CH;
#pragma unroll
    for (int i = 0; i < 4; i++)
        out[(size_t)(m0 + ty + i * 8) * C2CH + c0 + tx] = tile[tx][ty + i * 8];
}

// ---------------- transpose points1 -> split-bf16 feat cols [256..384) ----------------
__global__ void k_transpose_p1(const float* __restrict__ p1) {
    __shared__ float tile[32][33];
    const int b  = blockIdx.z;
    const int n0 = blockIdx.x * 32, c0 = blockIdx.y * 32;
    const int tx = threadIdx.x, ty = threadIdx.y;
    const float* in = p1 + (size_t)b * C1CH * NPTS;
#pragma unroll
    for (int i = 0; i < 4; i++)
        tile[ty + i * 8][tx] = in[(size_t)(c0 + ty + i * 8) * NPTS + n0 + tx];
    __syncthreads();
#pragma unroll
    for (int i = 0; i < 4; i++) {
        const int n = n0 + ty + i * 8;
        const size_t o = (size_t)(b * NPTS + n) * KIN + C2CH + c0 + tx;
        __nv_bfloat16 h, l;
        split_bf16(tile[tx][ty + i * 8], h, l);
        g_featH[o] = h; g_featL[o] = l;
    }
}

// ---------------- 3-NN over M=1024 (xyz2 staged in SMEM) ----------------
__global__ void k_knn(const float* __restrict__ xyz1, const float* __restrict__ xyz2) {
    __shared__ float4 s2[MPTS];
    const int b   = blockIdx.y;
    const int tid = threadIdx.x;
    const float* x2 = xyz2 + (size_t)b * 3 * MPTS;
    for (int m = tid; m < MPTS; m += 256)
        s2[m] = make_float4(x2[m], x2[m + MPTS], x2[m + 2 * MPTS], 0.f);
    __syncthreads();

    const int n = blockIdx.x * 256 + tid;
    const float* x1 = xyz1 + (size_t)b * 3 * NPTS;
    const float px = x1[n], py = x1[n + NPTS], pz = x1[n + 2 * NPTS];

    float d0 = 3.4e38f, d1 = 3.4e38f, d2 = 3.4e38f;
    int   i0 = 0, i1 = 0, i2 = 0;
#pragma unroll 4
    for (int m = 0; m < MPTS; m++) {
        const float4 q = s2[m];
        const float dx = px - q.x, dy = py - q.y, dz = pz - q.z;
        const float d = fmaf(dx, dx, fmaf(dy, dy, dz * dz));
        if (d < d2) {
            if (d < d1) {
                d2 = d1; i2 = i1;
                if (d < d0) { d1 = d0; i1 = i0; d0 = d; i0 = m; }
                else        { d1 = d;  i1 = m; }
            } else { d2 = d; i2 = m; }
        }
    }
    d0 = fmaxf(d0, 1e-10f); d1 = fmaxf(d1, 1e-10f); d2 = fmaxf(d2, 1e-10f);
    const float w0 = 1.f / d0, w1 = 1.f / d1, w2 = 1.f / d2;
    const float inv = 1.f / (w0 + w1 + w2);
    const int row = b * NPTS + n;
    g_idx[row * 3 + 0] = i0; g_idx[row * 3 + 1] = i1; g_idx[row * 3 + 2] = i2;
    g_wgt[row * 3 + 0] = w0 * inv; g_wgt[row * 3 + 1] = w1 * inv; g_wgt[row * 3 + 2] = w2 * inv;
}

// -------- weighted gather -> split-bf16 feat cols [0..256) (warp per row) --------
__global__ void k_interp() {
    const int tid  = threadIdx.x;
    const int warp = tid >> 5, lane = tid & 31;
    const int row  = blockIdx.x * 4 + warp;
    const int b    = row >> 12;
    const int i0 = g_idx[row * 3 + 0], i1 = g_idx[row * 3 + 1], i2 = g_idx[row * 3 + 2];
    const float w0 = g_wgt[row * 3 + 0], w1 = g_wgt[row * 3 + 1], w2 = g_wgt[row * 3 + 2];
    const float4* f0 = (const float4*)(g_p2t + ((size_t)b * MPTS + i0) * C2CH);
    const float4* f1 = (const float4*)(g_p2t + ((size_t)b * MPTS + i1) * C2CH);
    const float4* f2 = (const float4*)(g_p2t + ((size_t)b * MPTS + i2) * C2CH);
    union { __nv_bfloat16 b8[8]; uint4 u; } uh, ul;
#pragma unroll
    for (int half = 0; half < 2; half++) {
        const int j = lane * 2 + half;
        const float4 a = f0[j], c = f1[j], e = f2[j];
        float r[4];
        r[0] = fmaf(w0, a.x, fmaf(w1, c.x, w2 * e.x));
        r[1] = fmaf(w0, a.y, fmaf(w1, c.y, w2 * e.y));
        r[2] = fmaf(w0, a.z, fmaf(w1, c.z, w2 * e.z));
        r[3] = fmaf(w0, a.w, fmaf(w1, c.w, w2 * e.w));
#pragma unroll
        for (int q = 0; q < 4; q++)
            split_bf16(r[q], uh.b8[half * 4 + q], ul.b8[half * 4 + q]);
    }
    const size_t o = (size_t)row * KIN + lane * 8;
    *(uint4*)(g_featH + o) = uh.u;
    *(uint4*)(g_featL + o) = ul.u;
}

// ---------------- weight split prep ----------------
__global__ void k_prep_w(const float* __restrict__ W1, const float* __restrict__ W2) {
    const int i = blockIdx.x * 256 + threadIdx.x;
    if (i < OC * KIN) split_bf16(W1[i], g_w1h[i], g_w1l[i]);
    if (i < OC * OC)  split_bf16(W2[i], g_w2h[i], g_w2l[i]);
}

// ---------------- bf16x3-split GEMM via mma.sync (R14-proven config) ----------------
// CTA 128x128, 8 warps (4m x 2n), warp tile 32x64. K=16 stages, double-buffered
// cp.async (2x24KB = 48KB static). ldmatrix fragments, 48B rows (conflict-free).
// Epilogue emits deterministic per-CTA BN partials. Pointers bound in device code.
#define ARR  (128 * 48)            // bytes per matrix array per buffer (6144)
#define BUFB (4 * ARR)             // 24576

// shared mainloop compute for one K16 stage (identical to R14)
#define GEMM_STAGE_COMPUTE(sb)                                                  \
    do {                                                                        \
        uint32_t aH[2][4], aL[2][4], bH[8][2], bL[8][2];                        \
        _Pragma("unroll")                                                       \
        for (int mt = 0; mt < 2; mt++) {                                        \
            ldm_x4(aH[mt], (sb) + 0 * ARR + aoff + mt * 768);                   \
            ldm_x4(aL[mt], (sb) + 1 * ARR + aoff + mt * 768);                   \
        }                                                                       \
        _Pragma("unroll")                                                       \
        for (int np = 0; np < 4; np++) {                                        \
            uint32_t q[4];                                                      \
            ldm_x4(q, (sb) + 2 * ARR + boff + np * 768);                        \
            bH[2 * np][0] = q[0]; bH[2 * np][1] = q[1];                         \
            bH[2 * np + 1][0] = q[2]; bH[2 * np + 1][1] = q[3];                 \
            ldm_x4(q, (sb) + 3 * ARR + boff + np * 768);                        \
            bL[2 * np][0] = q[0]; bL[2 * np][1] = q[1];                         \
            bL[2 * np + 1][0] = q[2]; bL[2 * np + 1][1] = q[3];                 \
        }                                                                       \
        _Pragma("unroll")                                                       \
        for (int mt = 0; mt < 2; mt++)                                          \
            _Pragma("unroll")                                                   \
            for (int nt = 0; nt < 8; nt++) {                                    \
                mma16816(acc[mt][nt], aH[mt], bH[nt]);                          \
                mma16816(acc[mt][nt], aL[mt], bH[nt]);                          \
                mma16816(acc[mt][nt], aH[mt], bL[nt]);                          \
            }                                                                   \
    } while (0)

// shared epilogue: store C + fused deterministic BN partials
#define GEMM_EPILOGUE(smptr, C, psum, psq)                                      \
    do {                                                                        \
        _Pragma("unroll")                                                       \
        for (int mt = 0; mt < 2; mt++)                                          \
            _Pragma("unroll")                                                   \
            for (int nt = 0; nt < 8; nt++) {                                    \
                const int r = row0 + warp_m * 32 + mt * 16 + qm;                \
                const int c = col0 + warp_n * 64 + nt * 8 + qk;                 \
                *(float2*)&(C)[(size_t)r * OC + c] =                            \
                    make_float2(acc[mt][nt][0], acc[mt][nt][1]);                \
                *(float2*)&(C)[(size_t)(r + 8) * OC + c] =                      \
                    make_float2(acc[mt][nt][2], acc[mt][nt][3]);                \
            }                                                                   \
        __syncthreads();                                                        \
        float* scr = (float*)(smptr);                                           \
        _Pragma("unroll")                                                       \
        for (int nt = 0; nt < 8; nt++) {                                        \
            float s0 = acc[0][nt][0] + acc[0][nt][2] + acc[1][nt][0] + acc[1][nt][2]; \
            float s1 = acc[0][nt][1] + acc[0][nt][3] + acc[1][nt][1] + acc[1][nt][3]; \
            float q0 = acc[0][nt][0] * acc[0][nt][0] + acc[0][nt][2] * acc[0][nt][2]  \
                     + acc[1][nt][0] * acc[1][nt][0] + acc[1][nt][2] * acc[1][nt][2]; \
            float q1 = acc[0][nt][1] * acc[0][nt][1] + acc[0][nt][3] * acc[0][nt][3]  \
                     + acc[1][nt][1] * acc[1][nt][1] + acc[1][nt][3] * acc[1][nt][3]; \
            _Pragma("unroll")                                                   \
            for (int d = 16; d >= 4; d >>= 1) {                                 \
                s0 += __shfl_down_sync(0xffffffffu, s0, d);                     \
                s1 += __shfl_down_sync(0xffffffffu, s1, d);                     \
                q0 += __shfl_down_sync(0xffffffffu, q0, d);                     \
                q1 += __shfl_down_sync(0xffffffffu, q1, d);                     \
            }                                                                   \
            if (lane < 4) {                                                     \
                const int l64 = nt * 8 + lane * 2;                              \
                scr[wid * 64 + l64]           = s0;                             \
                scr[wid * 64 + l64 + 1]       = s1;                             \
                scr[512 + wid * 64 + l64]     = q0;                             \
                scr[512 + wid * 64 + l64 + 1] = q1;                             \
            }                                                                   \
        }                                                                       \
        __syncthreads();                                                        \
        if (tid < 128) {                                                        \
            const int half = tid >> 6, l64 = tid & 63;                          \
            float s = 0.f, q = 0.f;                                             \
            _Pragma("unroll")                                                   \
            for (int wm = 0; wm < 4; wm++) {                                    \
                s += scr[(half * 4 + wm) * 64 + l64];                           \
                q += scr[512 + (half * 4 + wm) * 64 + l64];                     \
            }                                                                   \
            (psum)[blockIdx.y * OC + col0 + tid] = s;                           \
            (psq) [blockIdx.y * OC + col0 + tid] = q;                           \
        }                                                                       \
    } while (0)

// ---- GEMM1: exact R14 body (bf16 A from g_feat, cp.async both sides) ----
__global__ __launch_bounds__(256, 2) void k_gemm1_mma() {
    constexpr int KDIM = KIN;
    __shared__ __align__(16) __nv_bfloat16 sm[2][4][128][24];
    const int tid  = threadIdx.x;
    const int lane = tid & 31, wid = tid >> 5;
    const int warp_m = wid & 3, warp_n = wid >> 2;
    const int row0 = blockIdx.y * 128, col0 = blockIdx.x * 128;

    const int arr = tid >> 6;
    const int r2  = (tid & 63) * 2;
    const __nv_bfloat16* g0 = (arr == 0) ? g_featH : (arr == 1) ? g_featL
                            : (arr == 2) ? g_w1h : g_w1l;
    const __nv_bfloat16* gp = g0 + (size_t)((arr < 2 ? row0 : col0) + r2) * KDIM;
    const uint32_t sbase = smem_u32(sm);
    const uint32_t sdst0 = sbase + (uint32_t)(arr * ARR + r2 * 48);

    const uint32_t aoff = (uint32_t)((warp_m * 32 + (lane & 15)) * 48 + ((lane & 16) ? 16 : 0));
    const uint32_t boff = (uint32_t)((warp_n * 64 + (lane & 7) + ((lane & 16) ? 8 : 0)) * 48
                                     + ((lane & 8) ? 16 : 0));
    const int qm = lane >> 2, qk = (lane & 3) * 2;

    float acc[2][8][4];
#pragma unroll
    for (int i = 0; i < 2; i++)
#pragma unroll
        for (int j = 0; j < 8; j++)
#pragma unroll
            for (int q = 0; q < 4; q++) acc[i][j][q] = 0.f;

    CP16(sdst0,      gp);
    CP16(sdst0 + 16, gp + 8);
    CP16(sdst0 + 48, gp + KDIM);
    CP16(sdst0 + 64, gp + KDIM + 8);
    CP_COMMIT();

    constexpr int NS = KDIM / 16;
    for (int t = 0; t < NS; t++) {
        const int buf = t & 1;
        CP_WAIT0();
        __syncthreads();
        if (t + 1 < NS) {
            const uint32_t d = sdst0 + (buf ^ 1) * BUFB;
            const __nv_bfloat16* gs = gp + (t + 1) * 16;
            CP16(d,      gs);
            CP16(d + 16, gs + 8);
            CP16(d + 48, gs + KDIM);
            CP16(d + 64, gs + KDIM + 8);
            CP_COMMIT();
        }
        const uint32_t sb = sbase + buf * BUFB;
        GEMM_STAGE_COMPUTE(sb);
    }
    GEMM_EPILOGUE(sm, g_h1, g_ps1, g_pq1);
}

// ---- GEMM2: fused BN1+ReLU+split A-loader (fp32 g_h1 -> bf16 h/l in-register) ----
__global__ __launch_bounds__(256, 2) void k_gemm2_mma() {
    constexpr int KDIM = OC;
    __shared__ __align__(16) __nv_bfloat16 sm[2][4][128][24];
    const int tid  = threadIdx.x;
    const int lane = tid & 31, wid = tid >> 5;
    const int warp_m = wid & 3, warp_n = wid >> 2;
    const int row0 = blockIdx.y * 128, col0 = blockIdx.x * 128;
    const bool isA = tid < 128;               // warps 0-3: A loader; 4-7: B loader

    // B loader mapping (tid 128..255): arr 2:Wh 3:Wl, rows r2,r2+1
    const int arr = tid >> 6;
    const int r2  = (tid & 63) * 2;
    const __nv_bfloat16* gpB = ((arr == 2) ? g_w2h : g_w2l) + (size_t)(col0 + r2) * KDIM;
    const uint32_t sbase = smem_u32(sm);
    const uint32_t sdstB = sbase + (uint32_t)(arr * ARR + r2 * 48);

    // A loader mapping (tid 0..127): one fp32 row each
    const float* gA = g_h1 + (size_t)(row0 + tid) * KDIM;

    const uint32_t aoff = (uint32_t)((warp_m * 32 + (lane & 15)) * 48 + ((lane & 16) ? 16 : 0));
    const uint32_t boff = (uint32_t)((warp_n * 64 + (lane & 7) + ((lane & 16) ? 8 : 0)) * 48
                                     + ((lane & 8) ? 16 : 0));
    const int qm = lane >> 2, qk = (lane & 3) * 2;

    float acc[2][8][4];
#pragma unroll
    for (int i = 0; i < 2; i++)
#pragma unroll
        for (int j = 0; j < 8; j++)
#pragma unroll
            for (int q = 0; q < 4; q++) acc[i][j][q] = 0.f;

    float4 v[4];
    // convert staged v (16 fp32 at k-range kc) -> bf16 h/l rows in sm[buf]
    auto cvst = [&](int kc, int buf) {
        __nv_bfloat16* dh = &sm[buf][0][tid][0];
        __nv_bfloat16* dl = &sm[buf][1][tid][0];
#pragma unroll
        for (int q = 0; q < 4; q++) {
            const float4 s = *(const float4*)(g_scale1 + kc + q * 4);
            const float4 b = *(const float4*)(g_bias1 + kc + q * 4);
            float r0 = fmaxf(fmaf(v[q].x, s.x, b.x), 0.f);
            float r1 = fmaxf(fmaf(v[q].y, s.y, b.y), 0.f);
            float r2f = fmaxf(fmaf(v[q].z, s.z, b.z), 0.f);
            float r3 = fmaxf(fmaf(v[q].w, s.w, b.w), 0.f);
            union { __nv_bfloat16 h4[4]; uint2 u; } ph, pl;
            split_bf16(r0, ph.h4[0], pl.h4[0]);
            split_bf16(r1, ph.h4[1], pl.h4[1]);
            split_bf16(r2f, ph.h4[2], pl.h4[2]);
            split_bf16(r3, ph.h4[3], pl.h4[3]);
            *(uint2*)(dh + q * 4) = ph.u;
            *(uint2*)(dl + q * 4) = pl.u;
        }
    };

    // prologue: stage 0 -> buf 0
    if (isA) {
#pragma unroll
        for (int q = 0; q < 4; q++) v[q] = *(const float4*)(gA + q * 4);
        cvst(0, 0);
    } else {
        CP16(sdstB,      gpB);
        CP16(sdstB + 16, gpB + 8);
        CP16(sdstB + 48, gpB + KDIM);
        CP16(sdstB + 64, gpB + KDIM + 8);
        CP_COMMIT();
    }

    constexpr int NS = KDIM / 16;
    for (int t = 0; t < NS; t++) {
        const int buf = t & 1;
        CP_WAIT0();
        __syncthreads();
        const bool hasNext = (t + 1 < NS);
        if (hasNext) {
            if (isA) {
                const float* gs = gA + (t + 1) * 16;
#pragma unroll
                for (int q = 0; q < 4; q++) v[q] = *(const float4*)(gs + q * 4);
            } else {
                const uint32_t d = sdstB + (buf ^ 1) * BUFB;
                const __nv_bfloat16* gs = gpB + (t + 1) * 16;
                CP16(d,      gs);
                CP16(d + 16, gs + 8);
                CP16(d + 48, gs + KDIM);
                CP16(d + 64, gs + KDIM + 8);
                CP_COMMIT();
            }
        }
        const uint32_t sb = sbase + buf * BUFB;
        GEMM_STAGE_COMPUTE(sb);
        if (hasNext && isA) cvst((t + 1) * 16, buf ^ 1);   // LDG latency hidden by MMAs
    }
    GEMM_EPILOGUE(sm, g_h2, g_ps2, g_pq2);
}

// ---------------- BN finalize: reduce 512 partial blocks, fixed order ----------------
__device__ __forceinline__ void fin_body(const float* __restrict__ psum,
                                         const float* __restrict__ psq,
                                         const float* __restrict__ gamma,
                                         const float* __restrict__ beta,
                                         float* __restrict__ scale,
                                         float* __restrict__ bias) {
    const int c = threadIdx.x;
    float s = 0.f, q = 0.f;
    for (int i = 0; i < NBLK; i++) { s += psum[i * OC + c]; q += psq[i * OC + c]; }
    const float invN = 1.f / (float)ROWS;
    const float mean = s * invN;
    const float var  = q * invN - mean * mean;
    const float sc   = gamma[c] * rsqrtf(var + EPSBN);
    scale[c] = sc;
    bias[c]  = fmaf(-mean, sc, beta[c]);
}
__global__ void k_fin1(const float* __restrict__ g, const float* __restrict__ b) {
    fin_body(g_ps1, g_pq1, g, b, g_scale1, g_bias1);
}
__global__ void k_fin2(const float* __restrict__ g, const float* __restrict__ b) {
    fin_body(g_ps2, g_pq2, g, b, g_scale2, g_bias2);
}

// ---------------- BN2+ReLU + transpose to (B, 256, N) ----------------
__global__ void k_out(float* __restrict__ out) {
    __shared__ float tile[32][33];
    const int b  = blockIdx.z;
    const int n0 = blockIdx.x * 32, c0 = blockIdx.y * 32;
    const int tx = threadIdx.x, ty = threadIdx.y;
#pragma unroll
    for (int i = 0; i < 4; i++) {
        const int n = n0 + ty + i * 8, c = c0 + tx;
        const float v = g_h2[(size_t)(b * NPTS + n) * OC + c];
        tile[ty + i * 8][tx] = fmaxf(fmaf(v, g_scale2[c], g_bias2[c]), 0.f);
    }
    __syncthreads();
    float* o = out + (size_t)b * OC * NPTS;
#pragma unroll
    for (int i = 0; i < 4; i++)
        o[(size_t)(c0 + ty + i * 8) * NPTS + n0 + tx] = tile[tx][ty + i * 8];
}

// ---------------- launch (only harness pointers cross the host/device boundary) ----
extern "C" void kernel_launch(void* const* d_in, const int* in_sizes, int n_in,
                              void* d_out, int out_size) {
    const float* xyz1    = (const float*)d_in[0];
    const float* xyz2    = (const float*)d_in[1];
    const float* points1 = (const float*)d_in[2];
    const float* points2 = (const float*)d_in[3];
    const float* W1      = (const float*)d_in[4];
    const float* gamma1  = (const float*)d_in[5];
    const float* beta1   = (const float*)d_in[6];
    const float* W2      = (const float*)d_in[7];
    const float* gamma2  = (const float*)d_in[8];
    const float* beta2   = (const float*)d_in[9];
    float* out = (float*)d_out;

    k_transpose_p2<<<dim3(MPTS / 32, C2CH / 32, BB), dim3(32, 8)>>>(points2);
    k_knn<<<dim3(NPTS / 256, BB), 256>>>(xyz1, xyz2);
    k_interp<<<ROWS / 4, 128>>>();
    k_transpose_p1<<<dim3(NPTS / 32, C1CH / 32, BB), dim3(32, 8)>>>(points1);
    k_prep_w<<<(OC * KIN + 255) / 256, 256>>>(W1, W2);

    k_gemm1_mma<<<dim3(OC / 128, ROWS / 128), 256>>>();
    k_fin1<<<1, 256>>>(gamma1, beta1);

    k_gemm2_mma<<<dim3(OC / 128, ROWS / 128), 256>>>();
    k_fin2<<<1, 256>>>(gamma2, beta2);

    k_out<<<dim3(NPTS / 32, OC / 32, BB), dim3(32, 8)>>>(out);
}